// round 7
// baseline (speedup 1.0000x reference)
#include <cuda_runtime.h>
#include <cuda_bf16.h>
#include <cuda_fp16.h>
#include <cstdint>

#define S_LEN 2048
#define D_HEAD 128
#define N_BH 32
#define BM 64
#define BN 64
#define NT (S_LEN / BN)
#define THREADS 128          // 4 warps, each owns 16 Q rows
#define STR 136              // padded row stride in 16-bit elems
#define LOG2E 1.4426950408889634f

// 16-bit element offsets
#define QH_E 0               // 64*136 = 8704
#define QL_E 8704
#define KH_E 17408
#define KL_E 26112
#define VF_E 34816
#define SMEM_ELEMS 43520     // *2 = 87040 bytes -> 2 CTAs/SM

static __device__ __forceinline__ float ex2f(float x) {
  float y; asm("ex2.approx.ftz.f32 %0, %1;" : "=f"(y) : "f"(x)); return y;
}
static __device__ __forceinline__ void mma16b(float d[4], const uint32_t a[4],
                                              uint32_t b0, uint32_t b1) {
  asm("mma.sync.aligned.m16n8k16.row.col.f32.bf16.bf16.f32 "
      "{%0,%1,%2,%3}, {%4,%5,%6,%7}, {%8,%9}, {%0,%1,%2,%3};"
      : "+f"(d[0]), "+f"(d[1]), "+f"(d[2]), "+f"(d[3])
      : "r"(a[0]), "r"(a[1]), "r"(a[2]), "r"(a[3]), "r"(b0), "r"(b1));
}
static __device__ __forceinline__ void mma16h(float d[4], const uint32_t a[4],
                                              uint32_t b0, uint32_t b1) {
  asm("mma.sync.aligned.m16n8k16.row.col.f32.f16.f16.f32 "
      "{%0,%1,%2,%3}, {%4,%5,%6,%7}, {%8,%9}, {%0,%1,%2,%3};"
      : "+f"(d[0]), "+f"(d[1]), "+f"(d[2]), "+f"(d[3])
      : "r"(a[0]), "r"(a[1]), "r"(a[2]), "r"(a[3]), "r"(b0), "r"(b1));
}
static __device__ __forceinline__ void ldsm4(uint32_t r[4], uint32_t addr) {
  asm volatile("ldmatrix.sync.aligned.m8n8.x4.shared.b16 {%0,%1,%2,%3}, [%4];"
               : "=r"(r[0]), "=r"(r[1]), "=r"(r[2]), "=r"(r[3]) : "r"(addr));
}
static __device__ __forceinline__ void ldsm4t(uint32_t r[4], uint32_t addr) {
  asm volatile("ldmatrix.sync.aligned.m8n8.x4.trans.shared.b16 {%0,%1,%2,%3}, [%4];"
               : "=r"(r[0]), "=r"(r[1]), "=r"(r[2]), "=r"(r[3]) : "r"(addr));
}
static __device__ __forceinline__ void split2(float x0, float x1,
                                              uint32_t& h, uint32_t& l) {
  __nv_bfloat16 h0 = __float2bfloat16_rn(x0);
  __nv_bfloat16 h1 = __float2bfloat16_rn(x1);
  __nv_bfloat162 hp = __halves2bfloat162(h0, h1);
  h = *reinterpret_cast<uint32_t*>(&hp);
  __nv_bfloat162 lp = __floats2bfloat162_rn(x0 - __bfloat162float(h0),
                                            x1 - __bfloat162float(h1));
  l = *reinterpret_cast<uint32_t*>(&lp);
}

extern __shared__ __align__(16) __nv_bfloat16 smbh[];

__global__ void __launch_bounds__(THREADS, 2)
fattn_h2(const float* __restrict__ Qg, const float* __restrict__ Kg,
         const float* __restrict__ Vg, float* __restrict__ Og)
{
  const int tid = threadIdx.x;
  const int bh  = blockIdx.y;
  const int q0  = blockIdx.x * BM;
  const size_t base = (size_t)bh * S_LEN * D_HEAD;

  const float* Qb = Qg + base + (size_t)q0 * D_HEAD;
  const float* Kb = Kg + base;
  const float* Vb = Vg + base;

  const int lane = tid & 31;
  const int wid  = tid >> 5;
  const int row0 = wid * 16;
  const uint32_t smu = (uint32_t)__cvta_generic_to_shared(smbh);

  // ---- load + split Q tile (64 x 128) into bf16 hi/lo planes ----
  #pragma unroll
  for (int i = 0; i < 16; ++i) {
    int idx = i * THREADS + tid;
    int row = idx >> 5;
    int c4  = (idx & 31) * 4;
    float4 v = *reinterpret_cast<const float4*>(Qb + row * D_HEAD + c4);
    uint32_t h01, l01, h23, l23;
    split2(v.x, v.y, h01, l01);
    split2(v.z, v.w, h23, l23);
    *reinterpret_cast<uint2*>(smbh + QH_E + row * STR + c4) = make_uint2(h01, h23);
    *reinterpret_cast<uint2*>(smbh + QL_E + row * STR + c4) = make_uint2(l01, l23);
  }

  // ldsm per-lane base addresses (byte units)
  const uint32_t qbase = smu + 2u * ((row0 + (lane & 15)) * STR + (lane >> 4) * 8);
  const uint32_t kbase = smu + 2u * (((lane & 7) + ((lane >> 4) << 3)) * STR
                                     + (((lane >> 3) & 1) << 3));
  const uint32_t vbase = smu + 2u * (((lane & 7) + (((lane >> 3) & 1) << 3)) * STR
                                     + ((lane >> 4) << 3));

  float o[16][4];
  #pragma unroll
  for (int n = 0; n < 16; ++n) { o[n][0] = o[n][1] = o[n][2] = o[n][3] = 0.f; }
  float mA = -INFINITY, mB = -INFINITY;
  float lA = 0.f, lB = 0.f;

  for (int t = 0; t < NT; ++t) {
    const float* Kt = Kb + (size_t)t * BN * D_HEAD;
    const float* Vt = Vb + (size_t)t * BN * D_HEAD;

    __syncthreads();   // previous iteration's plane reads complete

    // ---- convert K -> bf16 hi/lo planes, V -> fp16 plane (direct LDG) ----
    #pragma unroll
    for (int i = 0; i < 16; ++i) {
      int idx = i * THREADS + tid;
      int row = idx >> 5;
      int c4  = (idx & 31) * 4;
      float4 kv = *reinterpret_cast<const float4*>(Kt + row * D_HEAD + c4);
      uint32_t h01, l01, h23, l23;
      split2(kv.x, kv.y, h01, l01);
      split2(kv.z, kv.w, h23, l23);
      *reinterpret_cast<uint2*>(smbh + KH_E + row * STR + c4) = make_uint2(h01, h23);
      *reinterpret_cast<uint2*>(smbh + KL_E + row * STR + c4) = make_uint2(l01, l23);
      float4 vv = *reinterpret_cast<const float4*>(Vt + row * D_HEAD + c4);
      __half2 v01 = __floats2half2_rn(vv.x, vv.y);
      __half2 v23 = __floats2half2_rn(vv.z, vv.w);
      *reinterpret_cast<uint2*>(smbh + VF_E + row * STR + c4) =
          make_uint2(*reinterpret_cast<uint32_t*>(&v01),
                     *reinterpret_cast<uint32_t*>(&v23));
    }
    __syncthreads();

    // ---- S = Q K^T : 3-term split-bf16 ----
    float s[8][4];
    #pragma unroll
    for (int n = 0; n < 8; ++n) { s[n][0] = s[n][1] = s[n][2] = s[n][3] = 0.f; }

    #pragma unroll
    for (int c = 0; c < 8; ++c) {
      const int kc = c * 16;
      uint32_t qh[4], ql[4];
      ldsm4(qh, qbase + 2u * (QH_E + kc));
      ldsm4(ql, qbase + 2u * (QL_E + kc));
      #pragma unroll
      for (int n2 = 0; n2 < 4; ++n2) {
        uint32_t kh[4], kl[4];
        ldsm4(kh, kbase + 2u * (KH_E + n2 * 16 * STR + kc));
        ldsm4(kl, kbase + 2u * (KL_E + n2 * 16 * STR + kc));
        mma16b(s[2 * n2],     qh, kh[0], kh[1]);
        mma16b(s[2 * n2 + 1], qh, kh[2], kh[3]);
        mma16b(s[2 * n2],     qh, kl[0], kl[1]);
        mma16b(s[2 * n2 + 1], qh, kl[2], kl[3]);
        mma16b(s[2 * n2],     ql, kh[0], kh[1]);
        mma16b(s[2 * n2 + 1], ql, kh[2], kh[3]);
      }
    }

    // ---- online softmax ----
    float mx0 = s[0][0], mx1 = s[0][2];
    #pragma unroll
    for (int n = 0; n < 8; ++n) {
      mx0 = fmaxf(mx0, fmaxf(s[n][0], s[n][1]));
      mx1 = fmaxf(mx1, fmaxf(s[n][2], s[n][3]));
    }
    mx0 = fmaxf(mx0, __shfl_xor_sync(0xffffffffu, mx0, 1));
    mx0 = fmaxf(mx0, __shfl_xor_sync(0xffffffffu, mx0, 2));
    mx1 = fmaxf(mx1, __shfl_xor_sync(0xffffffffu, mx1, 1));
    mx1 = fmaxf(mx1, __shfl_xor_sync(0xffffffffu, mx1, 2));

    float mnA = fmaxf(mA, mx0);
    float mnB = fmaxf(mB, mx1);
    float aAc = ex2f((mA - mnA) * LOG2E);
    float aBc = ex2f((mB - mnB) * LOG2E);

    // P -> fp16 pairs; normalizer from the QUANTIZED values
    uint32_t p2[16];
    float psA = 0.f, psB = 0.f;
    #pragma unroll
    for (int n = 0; n < 8; ++n) {
      __half2 hA = __floats2half2_rn(ex2f((s[n][0] - mnA) * LOG2E),
                                     ex2f((s[n][1] - mnA) * LOG2E));
      __half2 hB = __floats2half2_rn(ex2f((s[n][2] - mnB) * LOG2E),
                                     ex2f((s[n][3] - mnB) * LOG2E));
      p2[2 * n]     = *reinterpret_cast<uint32_t*>(&hA);
      p2[2 * n + 1] = *reinterpret_cast<uint32_t*>(&hB);
      float2 fA = __half22float2(hA);
      float2 fB = __half22float2(hB);
      psA += fA.x + fA.y;
      psB += fB.x + fB.y;
    }
    psA += __shfl_xor_sync(0xffffffffu, psA, 1);
    psA += __shfl_xor_sync(0xffffffffu, psA, 2);
    psB += __shfl_xor_sync(0xffffffffu, psB, 1);
    psB += __shfl_xor_sync(0xffffffffu, psB, 2);

    lA = lA * aAc + psA;
    lB = lB * aBc + psB;
    mA = mnA; mB = mnB;

    #pragma unroll
    for (int n = 0; n < 16; ++n) {
      o[n][0] *= aAc; o[n][1] *= aAc;
      o[n][2] *= aBc; o[n][3] *= aBc;
    }

    // ---- O += P V : single-term fp16 ----
    #pragma unroll
    for (int c = 0; c < 4; ++c) {
      const int kc = c * 16;
      const uint32_t aP[4] = { p2[4 * c], p2[4 * c + 1], p2[4 * c + 2], p2[4 * c + 3] };
      #pragma unroll
      for (int n2 = 0; n2 < 8; ++n2) {
        uint32_t vh[4];
        ldsm4t(vh, vbase + 2u * (VF_E + kc * STR + n2 * 16));
        mma16h(o[2 * n2],     aP, vh[0], vh[1]);
        mma16h(o[2 * n2 + 1], aP, vh[2], vh[3]);
      }
    }
  }

  // ---- epilogue: O / l ----
  const int gid = lane >> 2;
  const int tg  = lane & 3;
  const float ilA = 1.f / lA;
  const float ilB = 1.f / lB;
  float* Ob = Og + base + (size_t)q0 * D_HEAD;
  #pragma unroll
  for (int n = 0; n < 16; ++n) {
    int col = n * 8 + 2 * tg;
    *reinterpret_cast<float2*>(Ob + (size_t)(row0 + gid) * D_HEAD + col) =
        make_float2(o[n][0] * ilA, o[n][1] * ilA);
    *reinterpret_cast<float2*>(Ob + (size_t)(row0 + gid + 8) * D_HEAD + col) =
        make_float2(o[n][2] * ilB, o[n][3] * ilB);
  }
}

extern "C" void kernel_launch(void* const* d_in, const int* in_sizes, int n_in,
                              void* d_out, int out_size) {
  const float* Q = (const float*)d_in[0];
  const float* K = (const float*)d_in[1];
  const float* V = (const float*)d_in[2];
  float* O = (float*)d_out;

  cudaFuncSetAttribute(fattn_h2, cudaFuncAttributeMaxDynamicSharedMemorySize,
                       SMEM_ELEMS * sizeof(__nv_bfloat16));
  dim3 grid(S_LEN / BM, N_BH);
  fattn_h2<<<grid, THREADS, SMEM_ELEMS * sizeof(__nv_bfloat16)>>>(Q, K, V, O);
}

// round 9
// speedup vs baseline: 1.2635x; 1.2635x over previous
#include <cuda_runtime.h>
#include <cuda_bf16.h>
#include <cuda_fp16.h>
#include <cstdint>

#define S_LEN 2048
#define D_HEAD 128
#define N_BH 32
#define BM 128
#define BN 64
#define NT (S_LEN / BN)      // 32
#define THREADS 256
#define STR 136
#define LOG2E 1.4426950408889634f

// 16-bit element offsets in smem
#define QH_E 0               // 128*136 = 17408
#define QL_E 17408
#define STG_E(s) (34816 + (s) * 26112)   // per stage: KH +0, KL +8704, VF +17408
#define SMEM_ELEMS (34816 + 3 * 26112)   // 113152 elems = 226304 B
#define KV_TILE_E 26112      // 3 planes * 8704
#define Q_TILE_E  34816      // 2 planes * 17408

// preconverted planes: g_q[bh][qtile][2*17408], g_kv[bh][ktile][3*8704]
static __device__ __nv_bfloat16 g_q[N_BH][S_LEN / BM][Q_TILE_E];
static __device__ __nv_bfloat16 g_kv[N_BH][NT][KV_TILE_E];

static __device__ __forceinline__ float ex2f(float x) {
  float y; asm("ex2.approx.ftz.f32 %0, %1;" : "=f"(y) : "f"(x)); return y;
}
static __device__ __forceinline__ void mma16b(float d[4], const uint32_t a[4],
                                              uint32_t b0, uint32_t b1) {
  asm("mma.sync.aligned.m16n8k16.row.col.f32.bf16.bf16.f32 "
      "{%0,%1,%2,%3}, {%4,%5,%6,%7}, {%8,%9}, {%0,%1,%2,%3};"
      : "+f"(d[0]), "+f"(d[1]), "+f"(d[2]), "+f"(d[3])
      : "r"(a[0]), "r"(a[1]), "r"(a[2]), "r"(a[3]), "r"(b0), "r"(b1));
}
static __device__ __forceinline__ void mma16h(float d[4], const uint32_t a[4],
                                              uint32_t b0, uint32_t b1) {
  asm("mma.sync.aligned.m16n8k16.row.col.f32.f16.f16.f32 "
      "{%0,%1,%2,%3}, {%4,%5,%6,%7}, {%8,%9}, {%0,%1,%2,%3};"
      : "+f"(d[0]), "+f"(d[1]), "+f"(d[2]), "+f"(d[3])
      : "r"(a[0]), "r"(a[1]), "r"(a[2]), "r"(a[3]), "r"(b0), "r"(b1));
}
static __device__ __forceinline__ void ldsm4(uint32_t r[4], uint32_t addr) {
  asm volatile("ldmatrix.sync.aligned.m8n8.x4.shared.b16 {%0,%1,%2,%3}, [%4];"
               : "=r"(r[0]), "=r"(r[1]), "=r"(r[2]), "=r"(r[3]) : "r"(addr));
}
static __device__ __forceinline__ void ldsm4t(uint32_t r[4], uint32_t addr) {
  asm volatile("ldmatrix.sync.aligned.m8n8.x4.trans.shared.b16 {%0,%1,%2,%3}, [%4];"
               : "=r"(r[0]), "=r"(r[1]), "=r"(r[2]), "=r"(r[3]) : "r"(addr));
}
static __device__ __forceinline__ void split2(float x0, float x1,
                                              uint32_t& h, uint32_t& l) {
  __nv_bfloat16 h0 = __float2bfloat16_rn(x0);
  __nv_bfloat16 h1 = __float2bfloat16_rn(x1);
  __nv_bfloat162 hp = __halves2bfloat162(h0, h1);
  h = *reinterpret_cast<uint32_t*>(&hp);
  __nv_bfloat162 lp = __floats2bfloat162_rn(x0 - __bfloat162float(h0),
                                            x1 - __bfloat162float(h1));
  l = *reinterpret_cast<uint32_t*>(&lp);
}
#define CPA16(dst, src) \
  asm volatile("cp.async.cg.shared.global [%0], [%1], 16;" :: "r"(dst), "l"(src))
#define CPA_COMMIT() asm volatile("cp.async.commit_group;" ::: "memory")

// ---------------- pre-pass: f32 -> split planes ----------------
__global__ void __launch_bounds__(256)
prepass(const float* __restrict__ Qg, const float* __restrict__ Kg,
        const float* __restrict__ Vg)
{
  int idx = blockIdx.x * 256 + threadIdx.x;        // 0 .. 2M-1
  int c4 = idx & 31;
  int s  = (idx >> 5) & (S_LEN - 1);
  int bh = idx >> 16;                              // 2048*32 float4 per bh
  int c  = c4 * 4;
  size_t g = (size_t)idx * 4;

  float4 q = *reinterpret_cast<const float4*>(Qg + g);
  uint32_t h01, l01, h23, l23;
  split2(q.x, q.y, h01, l01);
  split2(q.z, q.w, h23, l23);
  __nv_bfloat16* qd = &g_q[bh][s >> 7][(s & 127) * STR + c];
  *reinterpret_cast<uint2*>(qd)         = make_uint2(h01, h23);
  *reinterpret_cast<uint2*>(qd + 17408) = make_uint2(l01, l23);

  float4 k = *reinterpret_cast<const float4*>(Kg + g);
  split2(k.x, k.y, h01, l01);
  split2(k.z, k.w, h23, l23);
  __nv_bfloat16* kd = &g_kv[bh][s >> 6][(s & 63) * STR + c];
  *reinterpret_cast<uint2*>(kd)        = make_uint2(h01, h23);
  *reinterpret_cast<uint2*>(kd + 8704) = make_uint2(l01, l23);

  float4 v = *reinterpret_cast<const float4*>(Vg + g);
  __half2 v01 = __floats2half2_rn(v.x, v.y);
  __half2 v23 = __floats2half2_rn(v.z, v.w);
  *reinterpret_cast<uint2*>(kd + 17408) =
      make_uint2(*reinterpret_cast<uint32_t*>(&v01),
                 *reinterpret_cast<uint32_t*>(&v23));
}

extern __shared__ __align__(16) __nv_bfloat16 smbh[];

// ---------------- main attention kernel ----------------
__global__ void __launch_bounds__(THREADS, 1)
fattn_p(float* __restrict__ Og)
{
  const int tid = threadIdx.x;
  const int bh  = blockIdx.y;
  const int qt  = blockIdx.x;
  const size_t base = (size_t)bh * S_LEN * D_HEAD;

  const int lane = tid & 31;
  const int wid  = tid >> 5;
  const int row0 = wid * 16;
  const uint32_t smu = (uint32_t)__cvta_generic_to_shared(smbh);

  // ---- Q planes copy (group 0) ----
  {
    const char* src = (const char*)&g_q[bh][qt][0];
    #pragma unroll
    for (int i = 0; i < 17; ++i) {                 // 4352 chunks exact
      uint32_t off = (uint32_t)(i * THREADS + tid) * 16u;
      CPA16(smu + off, src + off);
    }
    CPA_COMMIT();
  }
  // ---- prologue: tiles 0,1 ----
  #pragma unroll
  for (int p = 0; p < 2; ++p) {
    const char* src = (const char*)&g_kv[bh][p][0];
    uint32_t db = (uint32_t)(STG_E(p) * 2);
    #pragma unroll
    for (int i = 0; i < 13; ++i) {
      int ch = i * THREADS + tid;
      if (ch < 3264) {
        uint32_t off = (uint32_t)ch * 16u;
        CPA16(smu + db + off, src + off);
      }
    }
    CPA_COMMIT();
  }

  // ldsm per-lane base addresses (byte units, plane-relative)
  const uint32_t qbase = smu + 2u * ((row0 + (lane & 15)) * STR + (lane >> 4) * 8);
  const uint32_t kbase = smu + 2u * (((lane & 7) + ((lane >> 4) << 3)) * STR
                                     + (((lane >> 3) & 1) << 3));
  const uint32_t vbase = smu + 2u * (((lane & 7) + (((lane >> 3) & 1) << 3)) * STR
                                     + ((lane >> 4) << 3));

  float o[16][4];
  #pragma unroll
  for (int n = 0; n < 16; ++n) { o[n][0] = o[n][1] = o[n][2] = o[n][3] = 0.f; }
  float mA = -INFINITY, mB = -INFINITY;
  float lA = 0.f, lB = 0.f;

  for (int t = 0; t < NT; ++t) {
    const int sb = t % 3;

    // wait for tile t (keep tile t+1 in flight)
    if (t < NT - 1) { asm volatile("cp.async.wait_group 1;" ::: "memory"); }
    else            { asm volatile("cp.async.wait_group 0;" ::: "memory"); }
    __syncthreads();   // tile t visible to all; stage (t+2)%3 fully consumed

    // issue tile t+2 into stage (t+2)%3
    if (t + 2 < NT) {
      const char* src = (const char*)&g_kv[bh][t + 2][0];
      uint32_t db = (uint32_t)(STG_E((t + 2) % 3) * 2);
      #pragma unroll
      for (int i = 0; i < 13; ++i) {
        int ch = i * THREADS + tid;
        if (ch < 3264) {
          uint32_t off = (uint32_t)ch * 16u;
          CPA16(smu + db + off, src + off);
        }
      }
      CPA_COMMIT();
    }

    const uint32_t khE = (uint32_t)STG_E(sb);
    const uint32_t klE = khE + 8704;
    const uint32_t vfE = khE + 17408;

    // ---- S = Q K^T : 3-term split-bf16 ----
    float s[8][4];
    #pragma unroll
    for (int n = 0; n < 8; ++n) { s[n][0] = s[n][1] = s[n][2] = s[n][3] = 0.f; }

    #pragma unroll
    for (int c = 0; c < 8; ++c) {
      const int kc = c * 16;
      uint32_t qh[4], ql[4];
      ldsm4(qh, qbase + 2u * (QH_E + kc));
      ldsm4(ql, qbase + 2u * (QL_E + kc));
      #pragma unroll
      for (int n2 = 0; n2 < 4; ++n2) {
        uint32_t kh[4], kl[4];
        ldsm4(kh, kbase + 2u * (khE + n2 * 16 * STR + kc));
        ldsm4(kl, kbase + 2u * (klE + n2 * 16 * STR + kc));
        mma16b(s[2 * n2],     qh, kh[0], kh[1]);
        mma16b(s[2 * n2 + 1], qh, kh[2], kh[3]);
        mma16b(s[2 * n2],     qh, kl[0], kl[1]);
        mma16b(s[2 * n2 + 1], qh, kl[2], kl[3]);
        mma16b(s[2 * n2],     ql, kh[0], kh[1]);
        mma16b(s[2 * n2 + 1], ql, kh[2], kh[3]);
      }
    }

    // ---- online softmax ----
    float mx0 = s[0][0], mx1 = s[0][2];
    #pragma unroll
    for (int n = 0; n < 8; ++n) {
      mx0 = fmaxf(mx0, fmaxf(s[n][0], s[n][1]));
      mx1 = fmaxf(mx1, fmaxf(s[n][2], s[n][3]));
    }
    mx0 = fmaxf(mx0, __shfl_xor_sync(0xffffffffu, mx0, 1));
    mx0 = fmaxf(mx0, __shfl_xor_sync(0xffffffffu, mx0, 2));
    mx1 = fmaxf(mx1, __shfl_xor_sync(0xffffffffu, mx1, 1));
    mx1 = fmaxf(mx1, __shfl_xor_sync(0xffffffffu, mx1, 2));

    float mnA = fmaxf(mA, mx0);
    float mnB = fmaxf(mB, mx1);
    float aAc = ex2f((mA - mnA) * LOG2E);
    float aBc = ex2f((mB - mnB) * LOG2E);

    uint32_t p2[16];
    float psA = 0.f, psB = 0.f;
    #pragma unroll
    for (int n = 0; n < 8; ++n) {
      __half2 hA = __floats2half2_rn(ex2f((s[n][0] - mnA) * LOG2E),
                                     ex2f((s[n][1] - mnA) * LOG2E));
      __half2 hB = __floats2half2_rn(ex2f((s[n][2] - mnB) * LOG2E),
                                     ex2f((s[n][3] - mnB) * LOG2E));
      p2[2 * n]     = *reinterpret_cast<uint32_t*>(&hA);
      p2[2 * n + 1] = *reinterpret_cast<uint32_t*>(&hB);
      float2 fA = __half22float2(hA);
      float2 fB = __half22float2(hB);
      psA += fA.x + fA.y;
      psB += fB.x + fB.y;
    }
    psA += __shfl_xor_sync(0xffffffffu, psA, 1);
    psA += __shfl_xor_sync(0xffffffffu, psA, 2);
    psB += __shfl_xor_sync(0xffffffffu, psB, 1);
    psB += __shfl_xor_sync(0xffffffffu, psB, 2);

    lA = lA * aAc + psA;
    lB = lB * aBc + psB;
    mA = mnA; mB = mnB;

    #pragma unroll
    for (int n = 0; n < 16; ++n) {
      o[n][0] *= aAc; o[n][1] *= aAc;
      o[n][2] *= aBc; o[n][3] *= aBc;
    }

    // ---- O += P V : single-term fp16 ----
    #pragma unroll
    for (int c = 0; c < 4; ++c) {
      const int kc = c * 16;
      const uint32_t aP[4] = { p2[4 * c], p2[4 * c + 1], p2[4 * c + 2], p2[4 * c + 3] };
      #pragma unroll
      for (int n2 = 0; n2 < 8; ++n2) {
        uint32_t vh[4];
        ldsm4t(vh, vbase + 2u * (vfE + kc * STR + n2 * 16));
        mma16h(o[2 * n2],     aP, vh[0], vh[1]);
        mma16h(o[2 * n2 + 1], aP, vh[2], vh[3]);
      }
    }
  }

  // ---- epilogue: O / l ----
  const int gid = lane >> 2;
  const int tg  = lane & 3;
  const float ilA = 1.f / lA;
  const float ilB = 1.f / lB;
  float* Ob = Og + base + (size_t)qt * BM * D_HEAD;
  #pragma unroll
  for (int n = 0; n < 16; ++n) {
    int col = n * 8 + 2 * tg;
    *reinterpret_cast<float2*>(Ob + (size_t)(row0 + gid) * D_HEAD + col) =
        make_float2(o[n][0] * ilA, o[n][1] * ilA);
    *reinterpret_cast<float2*>(Ob + (size_t)(row0 + gid + 8) * D_HEAD + col) =
        make_float2(o[n][2] * ilB, o[n][3] * ilB);
  }
}

extern "C" void kernel_launch(void* const* d_in, const int* in_sizes, int n_in,
                              void* d_out, int out_size) {
  const float* Q = (const float*)d_in[0];
  const float* K = (const float*)d_in[1];
  const float* V = (const float*)d_in[2];
  float* O = (float*)d_out;

  prepass<<<(N_BH * S_LEN * 32) / 256, 256>>>(Q, K, V);

  cudaFuncSetAttribute(fattn_p, cudaFuncAttributeMaxDynamicSharedMemorySize,
                       SMEM_ELEMS * sizeof(__nv_bfloat16));
  dim3 grid(S_LEN / BM, N_BH);
  fattn_p<<<grid, THREADS, SMEM_ELEMS * sizeof(__nv_bfloat16)>>>(O);
}